// round 15
// baseline (speedup 1.0000x reference)
#include <cuda_runtime.h>
#include <cuda_fp16.h>
#include <cstdint>

#define NB  32
#define C1  64
#define C2  384
#define HH  56
#define HW  3136
#define EPSV 1e-5f
#define XS  36            // X-tile row stride in 32-bit words (conflict-free for ldmatrix)

// ---------------- scratch (device globals; no allocation allowed) ----------------
__device__ uint32_t g_hp  [(size_t)NB * 192 * HW];    // expand out, packed fp16 ch-pair words
__device__ uint32_t g_weh [384 * 32];                  // w_expand fp16-pair words [c][j]
__device__ uint32_t g_wph [64 * 192];                  // w_proj   fp16-pair words [c][j]
__device__ float g_ctxsum[NB * C2];
__device__ float g_bias2 [NB * C2];
__device__ float g_s1[C2], g_sh1[C2];
__device__ float g_s2[C2], g_sh2[C2];
__device__ float g_s3[C1], g_sh3[C1];

// ---------------- helpers ----------------
__device__ __forceinline__ uint32_t hpack2(float f0, float f1) {
    __half2 H = __floats2half2_rn(f0, f1);
    return *reinterpret_cast<uint32_t*>(&H);
}

__device__ __forceinline__ void mma16816(float* c, const uint32_t* a, uint32_t b0, uint32_t b1) {
    asm volatile(
        "mma.sync.aligned.m16n8k16.row.col.f32.f16.f16.f32 "
        "{%0,%1,%2,%3},{%4,%5,%6,%7},{%8,%9},{%0,%1,%2,%3};"
        : "+f"(c[0]), "+f"(c[1]), "+f"(c[2]), "+f"(c[3])
        : "r"(a[0]), "r"(a[1]), "r"(a[2]), "r"(a[3]), "r"(b0), "r"(b1));
}

__device__ __forceinline__ void ldsm4(uint32_t* r, uint32_t addr) {
    asm volatile("ldmatrix.sync.aligned.m8n8.x4.shared.b16 {%0,%1,%2,%3},[%4];"
                 : "=r"(r[0]), "=r"(r[1]), "=r"(r[2]), "=r"(r[3]) : "r"(addr));
}

__device__ __forceinline__ void cpasync4(uint32_t dst, const void* src, bool valid) {
    asm volatile("cp.async.ca.shared.global [%0], [%1], 4, %2;"
                 :: "r"(dst), "l"(src), "r"(valid ? 4 : 0) : "memory");
}
__device__ __forceinline__ void cpasync16(uint32_t dst, const void* src) {
    asm volatile("cp.async.cg.shared.global [%0], [%1], 16;"
                 :: "r"(dst), "l"(src) : "memory");
}
__device__ __forceinline__ void cpasync_commit() {
    asm volatile("cp.async.commit_group;" ::: "memory");
}

__device__ __forceinline__ float clip6(float v) { return fminf(fmaxf(v, 0.f), 6.f); }

// ---------------- prep ----------------
__global__ void prep_kernel(const float* __restrict__ g1, const float* __restrict__ b1,
                            const float* __restrict__ m1, const float* __restrict__ v1,
                            const float* __restrict__ g2, const float* __restrict__ b2,
                            const float* __restrict__ m2, const float* __restrict__ v2,
                            const float* __restrict__ g3, const float* __restrict__ b3,
                            const float* __restrict__ m3, const float* __restrict__ v3,
                            const float* __restrict__ we, const float* __restrict__ wpj)
{
    int t = threadIdx.x;
    if (t < C2) {
        float s = g1[t] * rsqrtf(v1[t] + EPSV);
        g_s1[t] = s; g_sh1[t] = b1[t] - m1[t] * s;
        float s2 = g2[t] * rsqrtf(v2[t] + EPSV);
        g_s2[t] = s2; g_sh2[t] = b2[t] - m2[t] * s2;
    }
    if (t < C1) {
        float s = g3[t] * rsqrtf(v3[t] + EPSV);
        g_s3[t] = s; g_sh3[t] = b3[t] - m3[t] * s;
    }
    for (int i = t; i < NB * C2; i += blockDim.x) g_ctxsum[i] = 0.f;
    for (int i = t; i < 384 * 32; i += blockDim.x) {
        float2 wv = *(const float2*)(we + (size_t)i * 2);
        g_weh[i] = hpack2(wv.x, wv.y);
    }
    for (int i = t; i < 64 * 192; i += blockDim.x) {
        float2 wv = *(const float2*)(wpj + (size_t)i * 2);
        g_wph[i] = hpack2(wv.x, wv.y);
    }
}

// ======================= EXPAND: resident full-W, packed ch-pair output =====================
__global__ void __launch_bounds__(256, 2) expand_kernel(const float* __restrict__ x)
{
    extern __shared__ uint32_t sm[];
    uint32_t* xsh = sm;                    // [128 px][XS]
    uint32_t* wsh = xsh + 128 * XS;        // [384 ch][XS] full W

    const int n    = blockIdx.y;
    const int pix0 = blockIdx.x * 128;
    const int tid  = threadIdx.x;
    const int wid  = tid >> 5;
    const int lane = tid & 31;
    const int g    = lane >> 2;
    const int tq   = lane & 3;
    const int wm   = wid & 1;
    const int wn   = wid >> 1;

    const uint32_t xshb = (uint32_t)__cvta_generic_to_shared(xsh);
    const uint32_t wshb = (uint32_t)__cvta_generic_to_shared(wsh);
    const int lrow = (lane & 7) + ((lane >> 3) & 1) * 8;
    const int loff = (lrow * XS + ((lane >> 4) * 4)) * 4;

    const float* xn = x + (size_t)n * C1 * HW;

    // X tile
    for (int idx = tid; idx < 128 * 32; idx += 256) {
        int j = idx >> 7, p = idx & 127;
        int pg = pix0 + p;
        float f0 = 0.f, f1 = 0.f;
        if (pg < HW) {
            f0 = xn[(size_t)(2 * j) * HW + pg];
            f1 = xn[(size_t)(2 * j + 1) * HW + pg];
        }
        xsh[p * XS + j] = hpack2(f0, f1);
    }
    // full W
    {
        const uint4* src = (const uint4*)g_weh;
        for (int i = tid; i < 3072; i += 256) {
            int c = i >> 3, jq = (i & 7) * 4;
            *(uint4*)&wsh[c * XS + jq] = src[i];
        }
    }
    __syncthreads();

    for (int ct = 0; ct < 6; ++ct) {
        const int cbase = ct * 64;

        float acc[2][4][4];
        #pragma unroll
        for (int mt = 0; mt < 2; ++mt)
            #pragma unroll
            for (int nt = 0; nt < 4; ++nt)
                #pragma unroll
                for (int i = 0; i < 4; ++i) acc[mt][nt][i] = 0.f;

        #pragma unroll
        for (int s = 0; s < 4; ++s) {
            const int soff = s * 32;
            uint32_t ah[2][4], bh[2][4];
            #pragma unroll
            for (int mt = 0; mt < 2; ++mt) {
                uint32_t off = (uint32_t)((cbase + wm * 32 + mt * 16) * XS * 4 + soff) + loff;
                ldsm4(ah[mt], wshb + off);
            }
            #pragma unroll
            for (int q = 0; q < 2; ++q) {
                uint32_t off = (uint32_t)((wn * 32 + q * 16) * XS * 4 + soff) + loff;
                ldsm4(bh[q], xshb + off);
            }
            #pragma unroll
            for (int mt = 0; mt < 2; ++mt)
                #pragma unroll
                for (int q = 0; q < 2; ++q) {
                    mma16816(acc[mt][2*q],   ah[mt], bh[q][0], bh[q][2]);
                    mma16816(acc[mt][2*q+1], ah[mt], bh[q][1], bh[q][3]);
                }
        }

        // epilogue: BN1 + ReLU6 + pool + shuffle-packed store (ch-pair words)
        #pragma unroll
        for (int mt = 0; mt < 2; ++mt) {
            int c0 = cbase + wm * 32 + mt * 16 + g;   // g 0..7
            int c8 = c0 + 8;
            float s0 = g_s1[c0], h0 = g_sh1[c0];
            float s8 = g_s1[c8], h8 = g_sh1[c8];
            float rs0 = 0.f, rs8 = 0.f;
            #pragma unroll
            for (int nt = 0; nt < 4; ++nt) {
                int p = pix0 + wn * 32 + nt * 8 + 2 * tq;
                float v00 = clip6(s0 * acc[mt][nt][0] + h0);
                float v01 = clip6(s0 * acc[mt][nt][1] + h0);
                float v10 = clip6(s8 * acc[mt][nt][2] + h8);
                float v11 = clip6(s8 * acc[mt][nt][3] + h8);
                if (p < HW) { rs0 += v00 + v01; rs8 += v10 + v11; }
                // partner (g^1) values, same pixels
                float n00 = __shfl_xor_sync(0xffffffffu, v00, 4);
                float n01 = __shfl_xor_sync(0xffffffffu, v01, 4);
                float n10 = __shfl_xor_sync(0xffffffffu, v10, 4);
                float n11 = __shfl_xor_sync(0xffffffffu, v11, 4);
                if (((g & 1) == 0) && p < HW) {
                    uint32_t* pl0 = g_hp + ((size_t)(n * 192 + (c0 >> 1))) * HW + p;
                    *(uint2*)pl0 = make_uint2(hpack2(v00, n00), hpack2(v01, n01));
                    uint32_t* pl8 = g_hp + ((size_t)(n * 192 + (c8 >> 1))) * HW + p;
                    *(uint2*)pl8 = make_uint2(hpack2(v10, n10), hpack2(v11, n11));
                }
            }
            rs0 += __shfl_xor_sync(0xffffffffu, rs0, 1);
            rs0 += __shfl_xor_sync(0xffffffffu, rs0, 2);
            rs8 += __shfl_xor_sync(0xffffffffu, rs8, 1);
            rs8 += __shfl_xor_sync(0xffffffffu, rs8, 2);
            if (tq == 0) {
                atomicAdd(&g_ctxsum[n * C2 + c0], rs0);
                atomicAdd(&g_ctxsum[n * C2 + c8], rs8);
            }
        }
    }
}

// ---------------- context bias ----------------
__global__ void ctxbias_kernel(const float* __restrict__ wctx)
{
    __shared__ float cs[C2];
    const int n = blockIdx.x;
    const int o = threadIdx.x;
    cs[o] = g_ctxsum[n * C2 + o] * (1.f / (float)HW);
    __syncthreads();
    const float* wr = wctx + o * C2;
    float a = 0.f;
    #pragma unroll 4
    for (int c = 0; c < C2; ++c) a += cs[c] * wr[c];
    g_bias2[n * C2 + o] = g_s2[o] * a + g_sh2[o];
}

// ======================= PROJECT: fused dw3x3 + GEMM + BN3 + residual ================
#define JSTR 33                    // window: win[px_idx * JSTR + jw], px_idx = k*56+col
#define WINW (336 * JSTR)          // 11088 words (6 rows x 56 px)
#define XT   (128 * XS)            // 4608
#define WCH  (64 * XS)             // 2304
__global__ void __launch_bounds__(256, 2) project_kernel(const float* __restrict__ x,
                                                         const float* __restrict__ wdw,
                                                         float* __restrict__ out)
{
    extern __shared__ uint32_t sm[];
    uint32_t* win   = sm;                          // window (packed half2 ch-pairs)
    uint32_t* xsh   = win + WINW;                  // X tile for ldmatrix
    uint32_t* wc    = xsh + XT;                    // W chunk tile
    float*    wdw_s = (float*)(wc + WCH);          // 3456 dw weights
    float*    s2_s  = wdw_s + 3456;                // 384
    float*    b2_s  = s2_s + 384;                  // 384

    const int n    = blockIdx.y;
    const int pix0 = blockIdx.x * 128;
    const int tid  = threadIdx.x;
    const int wid  = tid >> 5;
    const int lane = tid & 31;
    const int g    = lane >> 2;
    const int tq   = lane & 3;
    const int wm   = wid & 1;
    const int wn   = wid >> 1;

    const uint32_t winb = (uint32_t)__cvta_generic_to_shared(win);
    const uint32_t xshb = (uint32_t)__cvta_generic_to_shared(xsh);
    const uint32_t wcb  = (uint32_t)__cvta_generic_to_shared(wc);
    const int lrow = (lane & 7) + ((lane >> 3) & 1) * 8;
    const int loff = (lrow * XS + ((lane >> 4) * 4)) * 4;

    const int rbase = pix0 / HH - 1;               // first window row (may be -1)

    // one-time loads
    for (int i = tid; i < 3456; i += 256) wdw_s[i] = wdw[i];
    for (int i = tid; i < C2; i += 256) { s2_s[i] = g_s2[i]; b2_s[i] = g_bias2[n * C2 + i]; }

    const uint32_t* hbase = g_hp + (size_t)n * 192 * HW;

    float acc[2][4][4];
    #pragma unroll
    for (int mt = 0; mt < 2; ++mt)
        #pragma unroll
        for (int nt = 0; nt < 4; ++nt)
            #pragma unroll
            for (int i = 0; i < 4; ++i) acc[mt][nt][i] = 0.f;

    const __half2 hz  = __floats2half2_rn(0.f, 0.f);
    const __half2 hs6 = __floats2half2_rn(6.f, 6.f);

    #pragma unroll 1
    for (int kt = 0; kt < 6; ++kt) {
        __syncthreads();           // protect win/wc/xsh reuse (also orders wdw_s on kt=0)

        // ---- fill W chunk (16B cp.async): 64 ch x 8 quad-groups = 512 ----
        {
            const uint4* src = (const uint4*)g_wph;
            for (int i = tid; i < 512; i += 256) {
                int c = i >> 3, j4 = (i & 7) * 4;
                cpasync16(wcb + (uint32_t)(c * XS + j4) * 4,
                          src + (c * 192 + kt * 32 + j4) / 4);
            }
        }
        // ---- fill halo window: 32 planes x 336 px (coalesced 4B cp.async) ----
        #pragma unroll 1
        for (int i = tid; i < 32 * 336; i += 256) {
            int jw = i / 336, px = i - jw * 336;
            int row = rbase + px / HH;
            int col = px % HH;
            bool v = (unsigned)row < (unsigned)HH;
            const uint32_t* sp_ = hbase + (size_t)(kt * 32 + jw) * HW + (v ? row * HH + col : 0);
            cpasync4(winb + (uint32_t)(px * JSTR + jw) * 4, sp_, v);
        }
        cpasync_commit();
        asm volatile("cp.async.wait_group 0;" ::: "memory");
        __syncthreads();

        // ---- dw 3x3 + bias + BN2 + ReLU6 (half2) -> xsh ----
        {
            const int jl = lane;
            const int c0 = (kt * 32 + jl) * 2;
            __half2 wp[9];
            #pragma unroll
            for (int t2 = 0; t2 < 9; ++t2)
                wp[t2] = __floats2half2_rn(wdw_s[c0 * 9 + t2], wdw_s[c0 * 9 + 9 + t2]);
            const __half2 s2p = __floats2half2_rn(s2_s[c0], s2_s[c0 + 1]);
            const __half2 b2p = __floats2half2_rn(b2_s[c0], b2_s[c0 + 1]);

            #pragma unroll
            for (int i = 0; i < 16; ++i) {
                const int pl  = wid * 16 + i;          // local pixel 0..127
                const int pgl = pix0 + pl;
                const int r   = pgl / HH;
                const int col = pgl - r * HH;
                const int k   = r - rbase;             // 1..4
                const int base = (k * HH + col) * JSTR + jl;
                const bool cl = col > 0, cr = col < HH - 1;
                const int bm = base - HH * JSTR, bp = base + HH * JSTR;

                __half2 a2 = hz;
                if (cl) {
                    a2 = __hfma2(*(const __half2*)&win[bm - JSTR],   wp[0], a2);
                    a2 = __hfma2(*(const __half2*)&win[base - JSTR], wp[3], a2);
                    a2 = __hfma2(*(const __half2*)&win[bp - JSTR],   wp[6], a2);
                }
                a2 = __hfma2(*(const __half2*)&win[bm],   wp[1], a2);
                a2 = __hfma2(*(const __half2*)&win[base], wp[4], a2);
                a2 = __hfma2(*(const __half2*)&win[bp],   wp[7], a2);
                if (cr) {
                    a2 = __hfma2(*(const __half2*)&win[bm + JSTR],   wp[2], a2);
                    a2 = __hfma2(*(const __half2*)&win[base + JSTR], wp[5], a2);
                    a2 = __hfma2(*(const __half2*)&win[bp + JSTR],   wp[8], a2);
                }
                __half2 h = __hfma2(a2, s2p, b2p);
                h = __hmax2(h, hz);
                h = __hmin2(h, hs6);
                xsh[pl * XS + jl] = *reinterpret_cast<uint32_t*>(&h);
            }
        }
        __syncthreads();

        // ---- MMA chunk ----
        #pragma unroll
        for (int s = 0; s < 4; ++s) {
            const int soff = s * 32;
            uint32_t ah[2][4], bh[2][4];
            #pragma unroll
            for (int mt = 0; mt < 2; ++mt) {
                uint32_t off = (uint32_t)((wm * 32 + mt * 16) * XS * 4 + soff) + loff;
                ldsm4(ah[mt], wcb + off);
            }
            #pragma unroll
            for (int q = 0; q < 2; ++q) {
                uint32_t off = (uint32_t)((wn * 32 + q * 16) * XS * 4 + soff) + loff;
                ldsm4(bh[q], xshb + off);
            }
            #pragma unroll
            for (int mt = 0; mt < 2; ++mt)
                #pragma unroll
                for (int q = 0; q < 2; ++q) {
                    mma16816(acc[mt][2*q],   ah[mt], bh[q][0], bh[q][2]);
                    mma16816(acc[mt][2*q+1], ah[mt], bh[q][1], bh[q][3]);
                }
        }
    }

    // epilogue: BN3 + residual
    #pragma unroll
    for (int mt = 0; mt < 2; ++mt) {
        int c0 = wm * 32 + mt * 16 + g;
        int c8 = c0 + 8;
        float s0 = g_s3[c0], h0 = g_sh3[c0];
        float s8 = g_s3[c8], h8 = g_sh3[c8];
        const float* xp0 = x   + ((size_t)(n * C1 + c0)) * HW;
        const float* xp8 = x   + ((size_t)(n * C1 + c8)) * HW;
        float*       op0 = out + ((size_t)(n * C1 + c0)) * HW;
        float*       op8 = out + ((size_t)(n * C1 + c8)) * HW;
        #pragma unroll
        for (int nt = 0; nt < 4; ++nt) {
            int p = pix0 + wn * 32 + nt * 8 + 2 * tq;
            if (p < HW) {
                float2 r0 = *(const float2*)(xp0 + p);
                float2 r8 = *(const float2*)(xp8 + p);
                *(float2*)(op0 + p) = make_float2(s0 * acc[mt][nt][0] + h0 + r0.x,
                                                  s0 * acc[mt][nt][1] + h0 + r0.y);
                *(float2*)(op8 + p) = make_float2(s8 * acc[mt][nt][2] + h8 + r8.x,
                                                  s8 * acc[mt][nt][3] + h8 + r8.y);
            }
        }
    }
}

// ---------------- launch ----------------
extern "C" void kernel_launch(void* const* d_in, const int* in_sizes, int n_in,
                              void* d_out, int out_size)
{
    const float* x        = (const float*)d_in[0];
    const float* w_expand = (const float*)d_in[1];
    const float* g1 = (const float*)d_in[2];
    const float* b1 = (const float*)d_in[3];
    const float* m1 = (const float*)d_in[4];
    const float* v1 = (const float*)d_in[5];
    const float* w_dw  = (const float*)d_in[6];
    const float* w_ctx = (const float*)d_in[7];
    const float* g2 = (const float*)d_in[8];
    const float* b2 = (const float*)d_in[9];
    const float* m2 = (const float*)d_in[10];
    const float* v2 = (const float*)d_in[11];
    const float* w_proj = (const float*)d_in[12];
    const float* g3 = (const float*)d_in[13];
    const float* b3 = (const float*)d_in[14];
    const float* m3 = (const float*)d_in[15];
    const float* v3 = (const float*)d_in[16];
    float* out = (float*)d_out;

    const int smem_expand  = (128 * XS + 384 * XS) * (int)sizeof(uint32_t);            // 73728
    const int smem_project = (WINW + XT + WCH + 3456 + 384 + 384) * (int)sizeof(uint32_t); // 88896
    cudaFuncSetAttribute((const void*)expand_kernel,
                         cudaFuncAttributeMaxDynamicSharedMemorySize, smem_expand);
    cudaFuncSetAttribute((const void*)project_kernel,
                         cudaFuncAttributeMaxDynamicSharedMemorySize, smem_project);

    prep_kernel<<<1, 512>>>(g1, b1, m1, v1, g2, b2, m2, v2, g3, b3, m3, v3,
                            w_expand, w_proj);
    expand_kernel<<<dim3(25, NB), 256, smem_expand>>>(x);
    ctxbias_kernel<<<NB, C2>>>(w_ctx);
    project_kernel<<<dim3(25, NB), 256, smem_project>>>(x, w_dw, out);
}

// round 16
// speedup vs baseline: 1.2603x; 1.2603x over previous
#include <cuda_runtime.h>
#include <cuda_fp16.h>
#include <cstdint>

#define NB  32
#define C1  64
#define C2  384
#define HH  56
#define HW  3136
#define EPSV 1e-5f
#define XS  36            // X-tile row stride in 32-bit words (conflict-free for ldmatrix)

// ---------------- scratch (device globals; no allocation allowed) ----------------
__device__ uint32_t g_hp  [(size_t)NB * HW * 192];    // expand out, INTERLEAVED [n][px][jw]
__device__ uint32_t g_weh [384 * 32];                  // w_expand fp16-pair words [c][j]
__device__ uint32_t g_wph [64 * 192];                  // w_proj   fp16-pair words [c][j]
__device__ float g_ctxsum[NB * C2];
__device__ float g_bias2 [NB * C2];
__device__ float g_s1[C2], g_sh1[C2];
__device__ float g_s2[C2], g_sh2[C2];
__device__ float g_s3[C1], g_sh3[C1];

// ---------------- helpers ----------------
__device__ __forceinline__ uint32_t hpack2(float f0, float f1) {
    __half2 H = __floats2half2_rn(f0, f1);
    return *reinterpret_cast<uint32_t*>(&H);
}

__device__ __forceinline__ void mma16816(float* c, const uint32_t* a, uint32_t b0, uint32_t b1) {
    asm volatile(
        "mma.sync.aligned.m16n8k16.row.col.f32.f16.f16.f32 "
        "{%0,%1,%2,%3},{%4,%5,%6,%7},{%8,%9},{%0,%1,%2,%3};"
        : "+f"(c[0]), "+f"(c[1]), "+f"(c[2]), "+f"(c[3])
        : "r"(a[0]), "r"(a[1]), "r"(a[2]), "r"(a[3]), "r"(b0), "r"(b1));
}

__device__ __forceinline__ void ldsm4(uint32_t* r, uint32_t addr) {
    asm volatile("ldmatrix.sync.aligned.m8n8.x4.shared.b16 {%0,%1,%2,%3},[%4];"
                 : "=r"(r[0]), "=r"(r[1]), "=r"(r[2]), "=r"(r[3]) : "r"(addr));
}

__device__ __forceinline__ void cpasync16(uint32_t dst, const void* src) {
    asm volatile("cp.async.cg.shared.global [%0], [%1], 16;"
                 :: "r"(dst), "l"(src) : "memory");
}
__device__ __forceinline__ void cpasync16z(uint32_t dst, const void* src, bool valid) {
    asm volatile("cp.async.cg.shared.global [%0], [%1], 16, %2;"
                 :: "r"(dst), "l"(src), "r"(valid ? 16 : 0) : "memory");
}
__device__ __forceinline__ void cpasync_commit() {
    asm volatile("cp.async.commit_group;" ::: "memory");
}

__device__ __forceinline__ float clip6(float v) { return fminf(fmaxf(v, 0.f), 6.f); }

// ---------------- prep ----------------
__global__ void prep_kernel(const float* __restrict__ g1, const float* __restrict__ b1,
                            const float* __restrict__ m1, const float* __restrict__ v1,
                            const float* __restrict__ g2, const float* __restrict__ b2,
                            const float* __restrict__ m2, const float* __restrict__ v2,
                            const float* __restrict__ g3, const float* __restrict__ b3,
                            const float* __restrict__ m3, const float* __restrict__ v3,
                            const float* __restrict__ we, const float* __restrict__ wpj)
{
    int t = threadIdx.x;
    if (t < C2) {
        float s = g1[t] * rsqrtf(v1[t] + EPSV);
        g_s1[t] = s; g_sh1[t] = b1[t] - m1[t] * s;
        float s2 = g2[t] * rsqrtf(v2[t] + EPSV);
        g_s2[t] = s2; g_sh2[t] = b2[t] - m2[t] * s2;
    }
    if (t < C1) {
        float s = g3[t] * rsqrtf(v3[t] + EPSV);
        g_s3[t] = s; g_sh3[t] = b3[t] - m3[t] * s;
    }
    for (int i = t; i < NB * C2; i += blockDim.x) g_ctxsum[i] = 0.f;
    for (int i = t; i < 384 * 32; i += blockDim.x) {
        float2 wv = *(const float2*)(we + (size_t)i * 2);
        g_weh[i] = hpack2(wv.x, wv.y);
    }
    for (int i = t; i < 64 * 192; i += blockDim.x) {
        float2 wv = *(const float2*)(wpj + (size_t)i * 2);
        g_wph[i] = hpack2(wv.x, wv.y);
    }
}

// ======================= EXPAND: resident full-W, interleaved ch-pair output =====================
__global__ void __launch_bounds__(256, 2) expand_kernel(const float* __restrict__ x)
{
    extern __shared__ uint32_t sm[];
    uint32_t* xsh = sm;                    // [128 px][XS]
    uint32_t* wsh = xsh + 128 * XS;        // [384 ch][XS] full W

    const int n    = blockIdx.y;
    const int pix0 = blockIdx.x * 128;
    const int tid  = threadIdx.x;
    const int wid  = tid >> 5;
    const int lane = tid & 31;
    const int g    = lane >> 2;
    const int tq   = lane & 3;
    const int wm   = wid & 1;
    const int wn   = wid >> 1;

    const uint32_t xshb = (uint32_t)__cvta_generic_to_shared(xsh);
    const uint32_t wshb = (uint32_t)__cvta_generic_to_shared(wsh);
    const int lrow = (lane & 7) + ((lane >> 3) & 1) * 8;
    const int loff = (lrow * XS + ((lane >> 4) * 4)) * 4;

    const float* xn = x + (size_t)n * C1 * HW;

    // X tile
    for (int idx = tid; idx < 128 * 32; idx += 256) {
        int j = idx >> 7, p = idx & 127;
        int pg = pix0 + p;
        float f0 = 0.f, f1 = 0.f;
        if (pg < HW) {
            f0 = xn[(size_t)(2 * j) * HW + pg];
            f1 = xn[(size_t)(2 * j + 1) * HW + pg];
        }
        xsh[p * XS + j] = hpack2(f0, f1);
    }
    // full W
    {
        const uint4* src = (const uint4*)g_weh;
        for (int i = tid; i < 3072; i += 256) {
            int c = i >> 3, jq = (i & 7) * 4;
            *(uint4*)&wsh[c * XS + jq] = src[i];
        }
    }
    __syncthreads();

    uint32_t* hpn = g_hp + (size_t)n * HW * 192;

    for (int ct = 0; ct < 6; ++ct) {
        const int cbase = ct * 64;

        float acc[2][4][4];
        #pragma unroll
        for (int mt = 0; mt < 2; ++mt)
            #pragma unroll
            for (int nt = 0; nt < 4; ++nt)
                #pragma unroll
                for (int i = 0; i < 4; ++i) acc[mt][nt][i] = 0.f;

        #pragma unroll
        for (int s = 0; s < 4; ++s) {
            const int soff = s * 32;
            uint32_t ah[2][4], bh[2][4];
            #pragma unroll
            for (int mt = 0; mt < 2; ++mt) {
                uint32_t off = (uint32_t)((cbase + wm * 32 + mt * 16) * XS * 4 + soff) + loff;
                ldsm4(ah[mt], wshb + off);
            }
            #pragma unroll
            for (int q = 0; q < 2; ++q) {
                uint32_t off = (uint32_t)((wn * 32 + q * 16) * XS * 4 + soff) + loff;
                ldsm4(bh[q], xshb + off);
            }
            #pragma unroll
            for (int mt = 0; mt < 2; ++mt)
                #pragma unroll
                for (int q = 0; q < 2; ++q) {
                    mma16816(acc[mt][2*q],   ah[mt], bh[q][0], bh[q][2]);
                    mma16816(acc[mt][2*q+1], ah[mt], bh[q][1], bh[q][3]);
                }
        }

        // epilogue: BN1 + ReLU6 + pool + shuffle-paired interleaved store
        #pragma unroll
        for (int mt = 0; mt < 2; ++mt) {
            int c0 = cbase + wm * 32 + mt * 16 + g;
            int c8 = c0 + 8;
            float s0 = g_s1[c0], h0 = g_sh1[c0];
            float s8 = g_s1[c8], h8 = g_sh1[c8];
            float rs0 = 0.f, rs8 = 0.f;
            #pragma unroll
            for (int nt = 0; nt < 4; ++nt) {
                int p = pix0 + wn * 32 + nt * 8 + 2 * tq;
                float v00 = clip6(s0 * acc[mt][nt][0] + h0);
                float v01 = clip6(s0 * acc[mt][nt][1] + h0);
                float v10 = clip6(s8 * acc[mt][nt][2] + h8);
                float v11 = clip6(s8 * acc[mt][nt][3] + h8);
                if (p < HW) { rs0 += v00 + v01; rs8 += v10 + v11; }
                float n00 = __shfl_xor_sync(0xffffffffu, v00, 4);
                float n01 = __shfl_xor_sync(0xffffffffu, v01, 4);
                float n10 = __shfl_xor_sync(0xffffffffu, v10, 4);
                float n11 = __shfl_xor_sync(0xffffffffu, v11, 4);
                if (((g & 1) == 0) && p < HW) {
                    uint32_t* b0 = hpn + (size_t)p * 192 + (c0 >> 1);
                    b0[0]   = hpack2(v00, n00);        // px p,   jw c0/2
                    b0[192] = hpack2(v01, n01);        // px p+1
                    b0[4]   = hpack2(v10, n10);        // px p,   jw c8/2 = c0/2+4
                    b0[196] = hpack2(v11, n11);        // px p+1
                }
            }
            rs0 += __shfl_xor_sync(0xffffffffu, rs0, 1);
            rs0 += __shfl_xor_sync(0xffffffffu, rs0, 2);
            rs8 += __shfl_xor_sync(0xffffffffu, rs8, 1);
            rs8 += __shfl_xor_sync(0xffffffffu, rs8, 2);
            if (tq == 0) {
                atomicAdd(&g_ctxsum[n * C2 + c0], rs0);
                atomicAdd(&g_ctxsum[n * C2 + c8], rs8);
            }
        }
    }
}

// ---------------- context bias ----------------
__global__ void ctxbias_kernel(const float* __restrict__ wctx)
{
    __shared__ float cs[C2];
    const int n = blockIdx.x;
    const int o = threadIdx.x;
    cs[o] = g_ctxsum[n * C2 + o] * (1.f / (float)HW);
    __syncthreads();
    const float* wr = wctx + o * C2;
    float a = 0.f;
    #pragma unroll 4
    for (int c = 0; c < C2; ++c) a += cs[c] * wr[c];
    g_bias2[n * C2 + o] = g_s2[o] * a + g_sh2[o];
}

// ======================= PROJECT: fused dw3x3 + GEMM + BN3 + residual ================
#define WSTR 36                    // window row stride (words); win[px_local * WSTR + jw]
#define WINW (336 * WSTR)          // 12096 words (6 rows x 56 px)
#define XT   (128 * XS)            // 4608
#define WCH  (64 * XS)             // 2304
__global__ void __launch_bounds__(256, 2) project_kernel(const float* __restrict__ x,
                                                         const float* __restrict__ wdw,
                                                         float* __restrict__ out)
{
    extern __shared__ uint32_t sm[];
    uint32_t* win   = sm;                          // window (packed half2 ch-pairs)
    uint32_t* xsh   = win + WINW;                  // X tile for ldmatrix
    uint32_t* wc    = xsh + XT;                    // W chunk tile
    float*    wdw_s = (float*)(wc + WCH);          // 3456 dw weights
    float*    s2_s  = wdw_s + 3456;                // 384
    float*    b2_s  = s2_s + 384;                  // 384

    const int n    = blockIdx.y;
    const int pix0 = blockIdx.x * 128;
    const int tid  = threadIdx.x;
    const int wid  = tid >> 5;
    const int lane = tid & 31;
    const int g    = lane >> 2;
    const int tq   = lane & 3;
    const int wm   = wid & 1;
    const int wn   = wid >> 1;

    const uint32_t winb = (uint32_t)__cvta_generic_to_shared(win);
    const uint32_t xshb = (uint32_t)__cvta_generic_to_shared(xsh);
    const uint32_t wcb  = (uint32_t)__cvta_generic_to_shared(wc);
    const int lrow = (lane & 7) + ((lane >> 3) & 1) * 8;
    const int loff = (lrow * XS + ((lane >> 4) * 4)) * 4;

    const int rbase = pix0 / HH - 1;               // first window row (may be -1)

    // one-time loads
    for (int i = tid; i < 3456; i += 256) wdw_s[i] = wdw[i];
    for (int i = tid; i < C2; i += 256) { s2_s[i] = g_s2[i]; b2_s[i] = g_bias2[n * C2 + i]; }

    const uint32_t* hpn = g_hp + (size_t)n * HW * 192;

    float acc[2][4][4];
    #pragma unroll
    for (int mt = 0; mt < 2; ++mt)
        #pragma unroll
        for (int nt = 0; nt < 4; ++nt)
            #pragma unroll
            for (int i = 0; i < 4; ++i) acc[mt][nt][i] = 0.f;

    const __half2 hz  = __floats2half2_rn(0.f, 0.f);
    const __half2 hs6 = __floats2half2_rn(6.f, 6.f);

    #pragma unroll 1
    for (int kt = 0; kt < 6; ++kt) {
        __syncthreads();           // protect win/wc/xsh reuse (also orders wdw_s on kt=0)

        // ---- fill W chunk (16B cp.async): 64 ch x 8 quads ----
        {
            const uint4* src = (const uint4*)g_wph;
            for (int i = tid; i < 512; i += 256) {
                int c = i >> 3, j4 = (i & 7) * 4;
                cpasync16(wcb + (uint32_t)(c * XS + j4) * 4,
                          src + (c * 192 + kt * 32 + j4) / 4);
            }
        }
        // ---- fill halo window: 336 px x 8 16B-quads (interleaved source) ----
        #pragma unroll 1
        for (int i = tid; i < 2688; i += 256) {
            int px = i >> 3, q = (i & 7) * 4;      // px 0..335, q 0,4,..28
            int row = rbase + px / HH;
            int col = px - (px / HH) * HH;
            bool v = (unsigned)row < (unsigned)HH;
            const uint32_t* gp = hpn + (size_t)(v ? row * HH + col : 0) * 192 + kt * 32 + q;
            cpasync16z(winb + (uint32_t)(px * WSTR + q) * 4, gp, v);
        }
        cpasync_commit();
        asm volatile("cp.async.wait_group 0;" ::: "memory");
        __syncthreads();

        // ---- dw 3x3 + bias + BN2 + ReLU6 (half2) -> xsh ----
        {
            const int jl = lane;
            const int c0 = (kt * 32 + jl) * 2;
            __half2 wp[9];
            #pragma unroll
            for (int t2 = 0; t2 < 9; ++t2)
                wp[t2] = __floats2half2_rn(wdw_s[c0 * 9 + t2], wdw_s[c0 * 9 + 9 + t2]);
            const __half2 s2p = __floats2half2_rn(s2_s[c0], s2_s[c0 + 1]);
            const __half2 b2p = __floats2half2_rn(b2_s[c0], b2_s[c0 + 1]);

            #pragma unroll
            for (int i = 0; i < 16; ++i) {
                const int pl  = wid * 16 + i;          // local pixel 0..127
                const int pgl = pix0 + pl;
                const int r   = pgl / HH;
                const int col = pgl - r * HH;
                const int k   = r - rbase;             // 1..4
                const int base = (k * HH + col) * WSTR + jl;
                const bool cl = col > 0, cr = col < HH - 1;
                const int bm = base - HH * WSTR, bp = base + HH * WSTR;

                __half2 a2 = hz;
                if (cl) {
                    a2 = __hfma2(*(const __half2*)&win[bm - WSTR],   wp[0], a2);
                    a2 = __hfma2(*(const __half2*)&win[base - WSTR], wp[3], a2);
                    a2 = __hfma2(*(const __half2*)&win[bp - WSTR],   wp[6], a2);
                }
                a2 = __hfma2(*(const __half2*)&win[bm],   wp[1], a2);
                a2 = __hfma2(*(const __half2*)&win[base], wp[4], a2);
                a2 = __hfma2(*(const __half2*)&win[bp],   wp[7], a2);
                if (cr) {
                    a2 = __hfma2(*(const __half2*)&win[bm + WSTR],   wp[2], a2);
                    a2 = __hfma2(*(const __half2*)&win[base + WSTR], wp[5], a2);
                    a2 = __hfma2(*(const __half2*)&win[bp + WSTR],   wp[8], a2);
                }
                __half2 h = __hfma2(a2, s2p, b2p);
                h = __hmax2(h, hz);
                h = __hmin2(h, hs6);
                xsh[pl * XS + jl] = *reinterpret_cast<uint32_t*>(&h);
            }
        }
        __syncthreads();

        // ---- MMA chunk ----
        #pragma unroll
        for (int s = 0; s < 4; ++s) {
            const int soff = s * 32;
            uint32_t ah[2][4], bh[2][4];
            #pragma unroll
            for (int mt = 0; mt < 2; ++mt) {
                uint32_t off = (uint32_t)((wm * 32 + mt * 16) * XS * 4 + soff) + loff;
                ldsm4(ah[mt], wcb + off);
            }
            #pragma unroll
            for (int q = 0; q < 2; ++q) {
                uint32_t off = (uint32_t)((wn * 32 + q * 16) * XS * 4 + soff) + loff;
                ldsm4(bh[q], xshb + off);
            }
            #pragma unroll
            for (int mt = 0; mt < 2; ++mt)
                #pragma unroll
                for (int q = 0; q < 2; ++q) {
                    mma16816(acc[mt][2*q],   ah[mt], bh[q][0], bh[q][2]);
                    mma16816(acc[mt][2*q+1], ah[mt], bh[q][1], bh[q][3]);
                }
        }
    }

    // epilogue: BN3 + residual
    #pragma unroll
    for (int mt = 0; mt < 2; ++mt) {
        int c0 = wm * 32 + mt * 16 + g;
        int c8 = c0 + 8;
        float s0 = g_s3[c0], h0 = g_sh3[c0];
        float s8 = g_s3[c8], h8 = g_sh3[c8];
        const float* xp0 = x   + ((size_t)(n * C1 + c0)) * HW;
        const float* xp8 = x   + ((size_t)(n * C1 + c8)) * HW;
        float*       op0 = out + ((size_t)(n * C1 + c0)) * HW;
        float*       op8 = out + ((size_t)(n * C1 + c8)) * HW;
        #pragma unroll
        for (int nt = 0; nt < 4; ++nt) {
            int p = pix0 + wn * 32 + nt * 8 + 2 * tq;
            if (p < HW) {
                float2 r0 = *(const float2*)(xp0 + p);
                float2 r8 = *(const float2*)(xp8 + p);
                *(float2*)(op0 + p) = make_float2(s0 * acc[mt][nt][0] + h0 + r0.x,
                                                  s0 * acc[mt][nt][1] + h0 + r0.y);
                *(float2*)(op8 + p) = make_float2(s8 * acc[mt][nt][2] + h8 + r8.x,
                                                  s8 * acc[mt][nt][3] + h8 + r8.y);
            }
        }
    }
}

// ---------------- launch ----------------
extern "C" void kernel_launch(void* const* d_in, const int* in_sizes, int n_in,
                              void* d_out, int out_size)
{
    const float* x        = (const float*)d_in[0];
    const float* w_expand = (const float*)d_in[1];
    const float* g1 = (const float*)d_in[2];
    const float* b1 = (const float*)d_in[3];
    const float* m1 = (const float*)d_in[4];
    const float* v1 = (const float*)d_in[5];
    const float* w_dw  = (const float*)d_in[6];
    const float* w_ctx = (const float*)d_in[7];
    const float* g2 = (const float*)d_in[8];
    const float* b2 = (const float*)d_in[9];
    const float* m2 = (const float*)d_in[10];
    const float* v2 = (const float*)d_in[11];
    const float* w_proj = (const float*)d_in[12];
    const float* g3 = (const float*)d_in[13];
    const float* b3 = (const float*)d_in[14];
    const float* m3 = (const float*)d_in[15];
    const float* v3 = (const float*)d_in[16];
    float* out = (float*)d_out;

    const int smem_expand  = (128 * XS + 384 * XS) * (int)sizeof(uint32_t);            // 73728
    const int smem_project = (WINW + XT + WCH + 3456 + 384 + 384) * (int)sizeof(uint32_t); // 92928
    cudaFuncSetAttribute((const void*)expand_kernel,
                         cudaFuncAttributeMaxDynamicSharedMemorySize, smem_expand);
    cudaFuncSetAttribute((const void*)project_kernel,
                         cudaFuncAttributeMaxDynamicSharedMemorySize, smem_project);

    prep_kernel<<<1, 512>>>(g1, b1, m1, v1, g2, b2, m2, v2, g3, b3, m3, v3,
                            w_expand, w_proj);
    expand_kernel<<<dim3(25, NB), 256, smem_expand>>>(x);
    ctxbias_kernel<<<NB, C2>>>(w_ctx);
    project_kernel<<<dim3(25, NB), 256, smem_project>>>(x, w_dw, out);
}

// round 17
// speedup vs baseline: 1.2729x; 1.0099x over previous
#include <cuda_runtime.h>
#include <cuda_fp16.h>
#include <cstdint>

#define NB  32
#define C1  64
#define C2  384
#define HH  56
#define HW  3136
#define EPSV 1e-5f
#define XS  36            // X-tile row stride in 32-bit words (conflict-free for ldmatrix)

// ---------------- scratch (device globals; no allocation allowed) ----------------
__device__ uint32_t g_hp  [(size_t)NB * HW * 192];    // expand out, INTERLEAVED [n][px][jw]
__device__ uint32_t g_weh [384 * 32];                  // w_expand fp16-pair words [c][j]
__device__ uint32_t g_wph [64 * 192];                  // w_proj   fp16-pair words [c][j]
__device__ float g_ctxsum[NB * C2];
__device__ float g_bias2 [NB * C2];
__device__ float g_s1[C2], g_sh1[C2];
__device__ float g_s2[C2], g_sh2[C2];
__device__ float g_s3[C1], g_sh3[C1];

// ---------------- helpers ----------------
__device__ __forceinline__ uint32_t hpack2(float f0, float f1) {
    __half2 H = __floats2half2_rn(f0, f1);
    return *reinterpret_cast<uint32_t*>(&H);
}

__device__ __forceinline__ void mma16816(float* c, const uint32_t* a, uint32_t b0, uint32_t b1) {
    asm volatile(
        "mma.sync.aligned.m16n8k16.row.col.f32.f16.f16.f32 "
        "{%0,%1,%2,%3},{%4,%5,%6,%7},{%8,%9},{%0,%1,%2,%3};"
        : "+f"(c[0]), "+f"(c[1]), "+f"(c[2]), "+f"(c[3])
        : "r"(a[0]), "r"(a[1]), "r"(a[2]), "r"(a[3]), "r"(b0), "r"(b1));
}

__device__ __forceinline__ void ldsm4(uint32_t* r, uint32_t addr) {
    asm volatile("ldmatrix.sync.aligned.m8n8.x4.shared.b16 {%0,%1,%2,%3},[%4];"
                 : "=r"(r[0]), "=r"(r[1]), "=r"(r[2]), "=r"(r[3]) : "r"(addr));
}

__device__ __forceinline__ void cpasync16(uint32_t dst, const void* src) {
    asm volatile("cp.async.cg.shared.global [%0], [%1], 16;"
                 :: "r"(dst), "l"(src) : "memory");
}
__device__ __forceinline__ void cpasync16z(uint32_t dst, const void* src, bool valid) {
    asm volatile("cp.async.cg.shared.global [%0], [%1], 16, %2;"
                 :: "r"(dst), "l"(src), "r"(valid ? 16 : 0) : "memory");
}
__device__ __forceinline__ void cpasync_commit() {
    asm volatile("cp.async.commit_group;" ::: "memory");
}

__device__ __forceinline__ float clip6(float v) { return fminf(fmaxf(v, 0.f), 6.f); }

// ---------------- prep ----------------
__global__ void prep_kernel(const float* __restrict__ g1, const float* __restrict__ b1,
                            const float* __restrict__ m1, const float* __restrict__ v1,
                            const float* __restrict__ g2, const float* __restrict__ b2,
                            const float* __restrict__ m2, const float* __restrict__ v2,
                            const float* __restrict__ g3, const float* __restrict__ b3,
                            const float* __restrict__ m3, const float* __restrict__ v3,
                            const float* __restrict__ we, const float* __restrict__ wpj)
{
    int t = threadIdx.x;
    if (t < C2) {
        float s = g1[t] * rsqrtf(v1[t] + EPSV);
        g_s1[t] = s; g_sh1[t] = b1[t] - m1[t] * s;
        float s2 = g2[t] * rsqrtf(v2[t] + EPSV);
        g_s2[t] = s2; g_sh2[t] = b2[t] - m2[t] * s2;
    }
    if (t < C1) {
        float s = g3[t] * rsqrtf(v3[t] + EPSV);
        g_s3[t] = s; g_sh3[t] = b3[t] - m3[t] * s;
    }
    for (int i = t; i < NB * C2; i += blockDim.x) g_ctxsum[i] = 0.f;
    for (int i = t; i < 384 * 32; i += blockDim.x) {
        float2 wv = *(const float2*)(we + (size_t)i * 2);
        g_weh[i] = hpack2(wv.x, wv.y);
    }
    for (int i = t; i < 64 * 192; i += blockDim.x) {
        float2 wv = *(const float2*)(wpj + (size_t)i * 2);
        g_wph[i] = hpack2(wv.x, wv.y);
    }
}

// ======================= EXPAND: resident full-W + staged interleaved output =====================
__global__ void __launch_bounds__(256, 2) expand_kernel(const float* __restrict__ x)
{
    extern __shared__ uint32_t sm[];
    uint32_t* xsh   = sm;                    // [128 px][XS]
    uint32_t* wsh   = xsh + 128 * XS;        // [384 ch][XS] full W
    uint32_t* stage = wsh + 384 * XS;        // [128 px][36] chunk output stage

    const int n    = blockIdx.y;
    const int pix0 = blockIdx.x * 128;
    const int tid  = threadIdx.x;
    const int wid  = tid >> 5;
    const int lane = tid & 31;
    const int g    = lane >> 2;
    const int tq   = lane & 3;
    const int wm   = wid & 1;
    const int wn   = wid >> 1;

    const uint32_t xshb = (uint32_t)__cvta_generic_to_shared(xsh);
    const uint32_t wshb = (uint32_t)__cvta_generic_to_shared(wsh);
    const int lrow = (lane & 7) + ((lane >> 3) & 1) * 8;
    const int loff = (lrow * XS + ((lane >> 4) * 4)) * 4;

    const float* xn = x + (size_t)n * C1 * HW;

    // X tile
    for (int idx = tid; idx < 128 * 32; idx += 256) {
        int j = idx >> 7, p = idx & 127;
        int pg = pix0 + p;
        float f0 = 0.f, f1 = 0.f;
        if (pg < HW) {
            f0 = xn[(size_t)(2 * j) * HW + pg];
            f1 = xn[(size_t)(2 * j + 1) * HW + pg];
        }
        xsh[p * XS + j] = hpack2(f0, f1);
    }
    // full W
    {
        const uint4* src = (const uint4*)g_weh;
        for (int i = tid; i < 3072; i += 256) {
            int c = i >> 3, jq = (i & 7) * 4;
            *(uint4*)&wsh[c * XS + jq] = src[i];
        }
    }
    __syncthreads();

    uint32_t* hpn = g_hp + (size_t)n * HW * 192;

    for (int ct = 0; ct < 6; ++ct) {
        const int cbase = ct * 64;

        float acc[2][4][4];
        #pragma unroll
        for (int mt = 0; mt < 2; ++mt)
            #pragma unroll
            for (int nt = 0; nt < 4; ++nt)
                #pragma unroll
                for (int i = 0; i < 4; ++i) acc[mt][nt][i] = 0.f;

        #pragma unroll
        for (int s = 0; s < 4; ++s) {
            const int soff = s * 32;
            uint32_t ah[2][4], bh[2][4];
            #pragma unroll
            for (int mt = 0; mt < 2; ++mt) {
                uint32_t off = (uint32_t)((cbase + wm * 32 + mt * 16) * XS * 4 + soff) + loff;
                ldsm4(ah[mt], wshb + off);
            }
            #pragma unroll
            for (int q = 0; q < 2; ++q) {
                uint32_t off = (uint32_t)((wn * 32 + q * 16) * XS * 4 + soff) + loff;
                ldsm4(bh[q], xshb + off);
            }
            #pragma unroll
            for (int mt = 0; mt < 2; ++mt)
                #pragma unroll
                for (int q = 0; q < 2; ++q) {
                    mma16816(acc[mt][2*q],   ah[mt], bh[q][0], bh[q][2]);
                    mma16816(acc[mt][2*q+1], ah[mt], bh[q][1], bh[q][3]);
                }
        }

        // epilogue: BN1 + ReLU6 + pool + shuffle-paired STS to stage (conflict-free)
        #pragma unroll
        for (int mt = 0; mt < 2; ++mt) {
            int c0 = cbase + wm * 32 + mt * 16 + g;
            int c8 = c0 + 8;
            float s0 = g_s1[c0], h0 = g_sh1[c0];
            float s8 = g_s1[c8], h8 = g_sh1[c8];
            const int jwl = wm * 16 + mt * 8 + (g >> 1);   // chunk-local jw of c0-pair
            float rs0 = 0.f, rs8 = 0.f;
            #pragma unroll
            for (int nt = 0; nt < 4; ++nt) {
                int pl = wn * 32 + nt * 8 + 2 * tq;        // local pixel
                int p  = pix0 + pl;
                float v00 = clip6(s0 * acc[mt][nt][0] + h0);
                float v01 = clip6(s0 * acc[mt][nt][1] + h0);
                float v10 = clip6(s8 * acc[mt][nt][2] + h8);
                float v11 = clip6(s8 * acc[mt][nt][3] + h8);
                if (p < HW) { rs0 += v00 + v01; rs8 += v10 + v11; }
                float n00 = __shfl_xor_sync(0xffffffffu, v00, 4);
                float n01 = __shfl_xor_sync(0xffffffffu, v01, 4);
                float n10 = __shfl_xor_sync(0xffffffffu, v10, 4);
                float n11 = __shfl_xor_sync(0xffffffffu, v11, 4);
                if ((g & 1) == 0) {
                    stage[pl * 36 + jwl]           = hpack2(v00, n00);
                    stage[(pl + 1) * 36 + jwl]     = hpack2(v01, n01);
                    stage[pl * 36 + jwl + 4]       = hpack2(v10, n10);
                    stage[(pl + 1) * 36 + jwl + 4] = hpack2(v11, n11);
                }
            }
            rs0 += __shfl_xor_sync(0xffffffffu, rs0, 1);
            rs0 += __shfl_xor_sync(0xffffffffu, rs0, 2);
            rs8 += __shfl_xor_sync(0xffffffffu, rs8, 1);
            rs8 += __shfl_xor_sync(0xffffffffu, rs8, 2);
            if (tq == 0) {
                atomicAdd(&g_ctxsum[n * C2 + c0], rs0);
                atomicAdd(&g_ctxsum[n * C2 + c8], rs8);
            }
        }
        __syncthreads();
        // coalesced interleaved copy-out: 16B/thread, pixel's 32 words are 128B contiguous
        for (int i = tid; i < 1024; i += 256) {
            int pxl = i >> 3, q = (i & 7) * 4;
            int pg = pix0 + pxl;
            if (pg < HW) {
                uint4 v = *(uint4*)&stage[pxl * 36 + q];
                *(uint4*)(hpn + (size_t)pg * 192 + ct * 32 + q) = v;
            }
        }
        __syncthreads();
    }
}

// ---------------- context bias ----------------
__global__ void ctxbias_kernel(const float* __restrict__ wctx)
{
    __shared__ float cs[C2];
    const int n = blockIdx.x;
    const int o = threadIdx.x;
    cs[o] = g_ctxsum[n * C2 + o] * (1.f / (float)HW);
    __syncthreads();
    const float* wr = wctx + o * C2;
    float a = 0.f;
    #pragma unroll 4
    for (int c = 0; c < C2; ++c) a += cs[c] * wr[c];
    g_bias2[n * C2 + o] = g_s2[o] * a + g_sh2[o];
}

// ======================= PROJECT: fused dw3x3 + GEMM + BN3 + residual ================
#define WSTR 36                    // window row stride (words); win[px_local * WSTR + jw]
#define WINW (336 * WSTR)          // 12096 words (6 rows x 56 px)
#define XT   (128 * XS)            // 4608
#define WCH  (64 * XS)             // 2304
__global__ void __launch_bounds__(256, 2) project_kernel(const float* __restrict__ x,
                                                         const float* __restrict__ wdw,
                                                         float* __restrict__ out)
{
    extern __shared__ uint32_t sm[];
    uint32_t* win   = sm;                          // window (packed half2 ch-pairs)
    uint32_t* xsh   = win + WINW;                  // X tile for ldmatrix
    uint32_t* wc    = xsh + XT;                    // W chunk tile
    float*    wdw_s = (float*)(wc + WCH);          // 3456 dw weights
    float*    s2_s  = wdw_s + 3456;                // 384
    float*    b2_s  = s2_s + 384;                  // 384

    const int n    = blockIdx.y;
    const int pix0 = blockIdx.x * 128;
    const int tid  = threadIdx.x;
    const int wid  = tid >> 5;
    const int lane = tid & 31;
    const int g    = lane >> 2;
    const int tq   = lane & 3;
    const int wm   = wid & 1;
    const int wn   = wid >> 1;

    const uint32_t winb = (uint32_t)__cvta_generic_to_shared(win);
    const uint32_t xshb = (uint32_t)__cvta_generic_to_shared(xsh);
    const uint32_t wcb  = (uint32_t)__cvta_generic_to_shared(wc);
    const int lrow = (lane & 7) + ((lane >> 3) & 1) * 8;
    const int loff = (lrow * XS + ((lane >> 4) * 4)) * 4;

    const int rbase = pix0 / HH - 1;               // first window row (may be -1)

    // one-time loads
    for (int i = tid; i < 3456; i += 256) wdw_s[i] = wdw[i];
    for (int i = tid; i < C2; i += 256) { s2_s[i] = g_s2[i]; b2_s[i] = g_bias2[n * C2 + i]; }

    const uint32_t* hpn = g_hp + (size_t)n * HW * 192;

    float acc[2][4][4];
    #pragma unroll
    for (int mt = 0; mt < 2; ++mt)
        #pragma unroll
        for (int nt = 0; nt < 4; ++nt)
            #pragma unroll
            for (int i = 0; i < 4; ++i) acc[mt][nt][i] = 0.f;

    const __half2 hz  = __floats2half2_rn(0.f, 0.f);
    const __half2 hs6 = __floats2half2_rn(6.f, 6.f);

    #pragma unroll 1
    for (int kt = 0; kt < 6; ++kt) {
        __syncthreads();           // protect win/wc/xsh reuse (also orders wdw_s on kt=0)

        // ---- fill W chunk (16B cp.async): 64 ch x 8 quads ----
        {
            const uint4* src = (const uint4*)g_wph;
            for (int i = tid; i < 512; i += 256) {
                int c = i >> 3, j4 = (i & 7) * 4;
                cpasync16(wcb + (uint32_t)(c * XS + j4) * 4,
                          src + (c * 192 + kt * 32 + j4) / 4);
            }
        }
        // ---- fill halo window: 336 px x 8 16B-quads (interleaved source) ----
        #pragma unroll 1
        for (int i = tid; i < 2688; i += 256) {
            int px = i >> 3, q = (i & 7) * 4;      // px 0..335, q 0,4,..28
            int row = rbase + px / HH;
            int col = px - (px / HH) * HH;
            bool v = (unsigned)row < (unsigned)HH;
            const uint32_t* gp = hpn + (size_t)(v ? row * HH + col : 0) * 192 + kt * 32 + q;
            cpasync16z(winb + (uint32_t)(px * WSTR + q) * 4, gp, v);
        }
        cpasync_commit();
        asm volatile("cp.async.wait_group 0;" ::: "memory");
        __syncthreads();

        // ---- dw 3x3 + bias + BN2 + ReLU6 (half2) -> xsh ----
        {
            const int jl = lane;
            const int c0 = (kt * 32 + jl) * 2;
            __half2 wp[9];
            #pragma unroll
            for (int t2 = 0; t2 < 9; ++t2)
                wp[t2] = __floats2half2_rn(wdw_s[c0 * 9 + t2], wdw_s[c0 * 9 + 9 + t2]);
            const __half2 s2p = __floats2half2_rn(s2_s[c0], s2_s[c0 + 1]);
            const __half2 b2p = __floats2half2_rn(b2_s[c0], b2_s[c0 + 1]);

            #pragma unroll
            for (int i = 0; i < 16; ++i) {
                const int pl  = wid * 16 + i;          // local pixel 0..127
                const int pgl = pix0 + pl;
                const int r   = pgl / HH;
                const int col = pgl - r * HH;
                const int k   = r - rbase;             // 1..4
                const int base = (k * HH + col) * WSTR + jl;
                const bool cl = col > 0, cr = col < HH - 1;
                const int bm = base - HH * WSTR, bp = base + HH * WSTR;

                __half2 a2 = hz;
                if (cl) {
                    a2 = __hfma2(*(const __half2*)&win[bm - WSTR],   wp[0], a2);
                    a2 = __hfma2(*(const __half2*)&win[base - WSTR], wp[3], a2);
                    a2 = __hfma2(*(const __half2*)&win[bp - WSTR],   wp[6], a2);
                }
                a2 = __hfma2(*(const __half2*)&win[bm],   wp[1], a2);
                a2 = __hfma2(*(const __half2*)&win[base], wp[4], a2);
                a2 = __hfma2(*(const __half2*)&win[bp],   wp[7], a2);
                if (cr) {
                    a2 = __hfma2(*(const __half2*)&win[bm + WSTR],   wp[2], a2);
                    a2 = __hfma2(*(const __half2*)&win[base + WSTR], wp[5], a2);
                    a2 = __hfma2(*(const __half2*)&win[bp + WSTR],   wp[8], a2);
                }
                __half2 h = __hfma2(a2, s2p, b2p);
                h = __hmax2(h, hz);
                h = __hmin2(h, hs6);
                xsh[pl * XS + jl] = *reinterpret_cast<uint32_t*>(&h);
            }
        }
        __syncthreads();

        // ---- MMA chunk ----
        #pragma unroll
        for (int s = 0; s < 4; ++s) {
            const int soff = s * 32;
            uint32_t ah[2][4], bh[2][4];
            #pragma unroll
            for (int mt = 0; mt < 2; ++mt) {
                uint32_t off = (uint32_t)((wm * 32 + mt * 16) * XS * 4 + soff) + loff;
                ldsm4(ah[mt], wcb + off);
            }
            #pragma unroll
            for (int q = 0; q < 2; ++q) {
                uint32_t off = (uint32_t)((wn * 32 + q * 16) * XS * 4 + soff) + loff;
                ldsm4(bh[q], xshb + off);
            }
            #pragma unroll
            for (int mt = 0; mt < 2; ++mt)
                #pragma unroll
                for (int q = 0; q < 2; ++q) {
                    mma16816(acc[mt][2*q],   ah[mt], bh[q][0], bh[q][2]);
                    mma16816(acc[mt][2*q+1], ah[mt], bh[q][1], bh[q][3]);
                }
        }
    }

    // epilogue: BN3 + residual
    #pragma unroll
    for (int mt = 0; mt < 2; ++mt) {
        int c0 = wm * 32 + mt * 16 + g;
        int c8 = c0 + 8;
        float s0 = g_s3[c0], h0 = g_sh3[c0];
        float s8 = g_s3[c8], h8 = g_sh3[c8];
        const float* xp0 = x   + ((size_t)(n * C1 + c0)) * HW;
        const float* xp8 = x   + ((size_t)(n * C1 + c8)) * HW;
        float*       op0 = out + ((size_t)(n * C1 + c0)) * HW;
        float*       op8 = out + ((size_t)(n * C1 + c8)) * HW;
        #pragma unroll
        for (int nt = 0; nt < 4; ++nt) {
            int p = pix0 + wn * 32 + nt * 8 + 2 * tq;
            if (p < HW) {
                float2 r0 = *(const float2*)(xp0 + p);
                float2 r8 = *(const float2*)(xp8 + p);
                *(float2*)(op0 + p) = make_float2(s0 * acc[mt][nt][0] + h0 + r0.x,
                                                  s0 * acc[mt][nt][1] + h0 + r0.y);
                *(float2*)(op8 + p) = make_float2(s8 * acc[mt][nt][2] + h8 + r8.x,
                                                  s8 * acc[mt][nt][3] + h8 + r8.y);
            }
        }
    }
}

// ---------------- launch ----------------
extern "C" void kernel_launch(void* const* d_in, const int* in_sizes, int n_in,
                              void* d_out, int out_size)
{
    const float* x        = (const float*)d_in[0];
    const float* w_expand = (const float*)d_in[1];
    const float* g1 = (const float*)d_in[2];
    const float* b1 = (const float*)d_in[3];
    const float* m1 = (const float*)d_in[4];
    const float* v1 = (const float*)d_in[5];
    const float* w_dw  = (const float*)d_in[6];
    const float* w_ctx = (const float*)d_in[7];
    const float* g2 = (const float*)d_in[8];
    const float* b2 = (const float*)d_in[9];
    const float* m2 = (const float*)d_in[10];
    const float* v2 = (const float*)d_in[11];
    const float* w_proj = (const float*)d_in[12];
    const float* g3 = (const float*)d_in[13];
    const float* b3 = (const float*)d_in[14];
    const float* m3 = (const float*)d_in[15];
    const float* v3 = (const float*)d_in[16];
    float* out = (float*)d_out;

    const int smem_expand  = (128 * XS + 384 * XS + 128 * 36) * (int)sizeof(uint32_t);  // 92160
    const int smem_project = (WINW + XT + WCH + 3456 + 384 + 384) * (int)sizeof(uint32_t); // 92928
    cudaFuncSetAttribute((const void*)expand_kernel,
                         cudaFuncAttributeMaxDynamicSharedMemorySize, smem_expand);
    cudaFuncSetAttribute((const void*)project_kernel,
                         cudaFuncAttributeMaxDynamicSharedMemorySize, smem_project);

    prep_kernel<<<1, 512>>>(g1, b1, m1, v1, g2, b2, m2, v2, g3, b3, m3, v3,
                            w_expand, w_proj);
    expand_kernel<<<dim3(25, NB), 256, smem_expand>>>(x);
    ctxbias_kernel<<<NB, C2>>>(w_ctx);
    project_kernel<<<dim3(25, NB), 256, smem_project>>>(x, w_dw, out);
}